// round 7
// baseline (speedup 1.0000x reference)
#include <cuda_runtime.h>
#include <math.h>

// Problem constants (B=8, C=3, H=W=512, P=64, K=16)
#define BN        512          // B*N patches
#define DD        12288        // C*P*P
#define KR        16           // low rank
#define T1        256          // threads in pass1 CTA (128 row-pairs)
#define ITERS     96           // 12288 rows / 128 pairs
#define NW        8            // warps per pass1 CTA
#define NTRI      72           // per-lane triangle entries (36 small + 28 mixed + 8 anti-diag)
#define GCONST    22583.833392038037f   // d * ln(2*pi)

// Static scratch
__device__ float g_nll[BN];
__device__ float g_sc [BN][8];   // rdr, ld, sv2, ssg, srel, smin, bsum

// ---------------------------------------------------------------------------
// Pass 1 (everything but the final scalar combine): one CTA per patch,
// 128 lane-PAIRS. Both lanes of a pair process the SAME row; the odd lane
// works on the index-reversed vector b[j] = a[15-j], so one static 72-entry
// template covers the full 136-entry V^T D^-1 V triangle across the pair:
//   even lane (b=a):        small tri (k<=7), mixed k+q<15, anti-diag k+q=15
//   odd  lane (b=a o rev):  big tri (both>=8), mixed k+q>15, anti-diag (dup x0.5)
// Software-pipelined loads (next row prefetched before the FMA body).
// Patch-edge boundary diffs (vs upper/left neighbor) folded into the prologue.
// Then smem merge, 16x16 Cholesky, forward solve, per-patch NLL — all in-CTA.
// Identity: quad = r^T D^-1 r - w^T M^-1 w,  w = V^T D^-1 r  (V read ONCE).
// ---------------------------------------------------------------------------
__global__ void __launch_bounds__(T1, 1) pass1_kernel(
    const float* __restrict__ x0, const float* __restrict__ mu,
    const float* __restrict__ sigma, const float* __restrict__ V)
{
    const int pat = blockIdx.x;
    const int t   = threadIdx.x;
    const int par = t & 1;             // lane parity within pair
    const int pr  = t >> 1;            // pair id: 0..127
    const int b_  = pat >> 6;
    const int n   = pat & 63;
    const int gy  = n >> 3;
    const int gx  = n & 7;

    const float* __restrict__ mup = mu    + (size_t)pat * DD;
    const float* __restrict__ sgp = sigma + (size_t)pat * DD;
    const float* __restrict__ vp  = V     + (size_t)pat * DD * KR;
    const float* __restrict__ xp  = x0 + (size_t)b_ * 3 * 262144
                                       + (size_t)(gy * 64) * 512 + gx * 64;

    // ---- boundary partial: this CTA owns its TOP (vs gy-1) and LEFT (vs gx-1)
    // patch edges. 384 squared diffs spread over the 256 threads.
    float bsum = 0.0f;
#pragma unroll
    for (int ee = 0; ee < 2; ee++) {
        const int e = t + ee * 256;
        if (e < 192) {                         // dy edge (needs gy>0)
            if (gy > 0) {
                const int c = e >> 6, px = e & 63;
                const float d0 = mup[c * 4096 + px]
                               - mup[-8 * DD + c * 4096 + 4032 + px];
                bsum = fmaf(d0, d0, bsum);
            }
        } else if (e < 384) {                  // dx edge (needs gx>0)
            if (gx > 0) {
                const int j = e - 192, c = j >> 6, py = j & 63;
                const float d0 = mup[c * 4096 + py * 64]
                               - mup[-DD + c * 4096 + py * 64 + 63];
                bsum = fmaf(d0, d0, bsum);
            }
        }
    }

    float tri[NTRI];
    float wvh[8];
#pragma unroll
    for (int q = 0; q < NTRI; q++) tri[q] = 0.0f;
#pragma unroll
    for (int q = 0; q < 8; q++) wvh[q] = 0.0f;
    float rdr = 0.0f, ld = 0.0f, sv2 = 0.0f, ssg = 0.0f, srel = 0.0f;
    float smin = 3.402823466e38f;

    // ---- prefetch row 0
    int i = pr;
    float  nsg = sgp[i];
    float  nm  = mup[i];
    float  nx  = xp[(i >> 12) * 262144 + ((i >> 6) & 63) * 512 + (i & 63)];
    float4 nva = *(const float4*)(vp + (size_t)i * KR + par * 8);
    float4 nvb = *(const float4*)(vp + (size_t)i * KR + par * 8 + 4);

#pragma unroll 1
    for (int it = 0; it < ITERS; it++) {
        const float  csg = nsg, cm = nm, cx = nx;
        const float4 va = nva, vb = nvb;
        if (it + 1 < ITERS) {                  // prefetch next row
            i += 128;
            nsg = sgp[i];
            nm  = mup[i];
            nx  = xp[(i >> 12) * 262144 + ((i >> 6) & 63) * 512 + (i & 63)];
            nva = *(const float4*)(vp + (size_t)i * KR + par * 8);
            nvb = *(const float4*)(vp + (size_t)i * KR + par * 8 + 4);
        }

        const float s   = rsqrtf(csg);
        const float r   = cx - cm;
        const float gsv = s * r;
        rdr  = fmaf(gsv, gsv, rdr);
        ld  += __logf(csg);
        ssg += csg;
        const float u = fmaxf(0.3f - csg, 0.0f);
        srel = fmaf(u, u, srel);
        smin = fminf(smin, csg);

        // raw V^2 partial (own half only -> no duplication across the pair)
        float t2 = 0.0f;
        t2 = fmaf(va.x, va.x, t2); t2 = fmaf(va.y, va.y, t2);
        t2 = fmaf(va.z, va.z, t2); t2 = fmaf(va.w, va.w, t2);
        t2 = fmaf(vb.x, vb.x, t2); t2 = fmaf(vb.y, vb.y, t2);
        t2 = fmaf(vb.z, vb.z, t2); t2 = fmaf(vb.w, vb.w, t2);
        sv2 += t2;

        float raw[8];
        raw[0]=va.x*s; raw[1]=va.y*s; raw[2]=va.z*s; raw[3]=va.w*s;
        raw[4]=vb.x*s; raw[5]=vb.y*s; raw[6]=vb.z*s; raw[7]=vb.w*s;

        // build b: even lane b = a ; odd lane b[j] = a[15-j]
        float b[16];
#pragma unroll
        for (int j = 0; j < 8; j++) b[j] = par ? raw[7 - j] : raw[j];
#pragma unroll
        for (int j = 0; j < 8; j++) {
            const float snd = par ? raw[j] : raw[7 - j];
            b[8 + j] = __shfl_xor_sync(0xffffffffu, snd, 1);
        }

        // wv on lower-half of b: even -> logical wv[0..7]; odd -> wv[15..8]
#pragma unroll
        for (int j = 0; j < 8; j++) wvh[j] = fmaf(b[j], gsv, wvh[j]);

        // triangle: 36 small + 28 mixed + 8 anti-diagonal
        int c = 0;
#pragma unroll
        for (int k = 0; k < 8; k++)
#pragma unroll
            for (int q = 0; q <= k; q++) {
                tri[c] = fmaf(b[k], b[q], tri[c]);
                c++;
            }
#pragma unroll
        for (int k = 8; k < 15; k++)
#pragma unroll
            for (int q = 0; q < 15 - k; q++) {
                tri[c] = fmaf(b[k], b[q], tri[c]);
                c++;
            }
#pragma unroll
        for (int k = 8; k < 16; k++) {
            tri[c] = fmaf(b[k], b[15 - k], tri[c]);
            c++;
        }
    }

    // butterfly over SAME-PARITY lanes (even offsets only)
#pragma unroll
    for (int off = 16; off > 1; off >>= 1) {
#pragma unroll
        for (int q = 0; q < NTRI; q++) tri[q] += __shfl_xor_sync(0xffffffffu, tri[q], off);
#pragma unroll
        for (int q = 0; q < 8; q++) wvh[q] += __shfl_xor_sync(0xffffffffu, wvh[q], off);
    }
    // stats: full butterfly (pair-duplicated row stats -> x0.5 later; bsum not dup'd)
#pragma unroll
    for (int off = 16; off > 0; off >>= 1) {
        rdr  += __shfl_xor_sync(0xffffffffu, rdr,  off);
        ld   += __shfl_xor_sync(0xffffffffu, ld,   off);
        sv2  += __shfl_xor_sync(0xffffffffu, sv2,  off);
        ssg  += __shfl_xor_sync(0xffffffffu, ssg,  off);
        srel += __shfl_xor_sync(0xffffffffu, srel, off);
        bsum += __shfl_xor_sync(0xffffffffu, bsum, off);
        smin  = fminf(smin, __shfl_xor_sync(0xffffffffu, smin, off));
    }

    __shared__ float wp [NW][2 * NTRI];   // [w][par*72 + r]
    __shared__ float wpv[NW][16];         // [w][par*8 + j]
    __shared__ float wps[NW][8];
    __shared__ float sM[16][17];
    __shared__ float sw[16];
    __shared__ float srd[2];

    {
        const int w = t >> 5, l = t & 31, g = l >> 1, h = l & 1;
        for (int r = g; r < NTRI; r += 16) wp[w][h * NTRI + r] = tri[r];
        if (g < 8) wpv[w][h * 8 + g] = wvh[g];
        if (l == 0) {
            wps[w][0] = rdr;  wps[w][1] = ld;  wps[w][2] = sv2;
            wps[w][3] = ssg;  wps[w][4] = srel; wps[w][5] = smin;
            wps[w][6] = bsum;
        }
    }
    __syncthreads();

    // ---- merge: rebuild M(16x16) from the two entry classes ----
    if (t < 136) {
        // decode (k,q), q<=k, from linear index t
        int k = 0;
        while ((k + 1) * (k + 2) / 2 <= t) k++;
        const int q = t - k * (k + 1) / 2;

        float val;
        if (k + q == 15 && k >= 8) {                     // anti-diag (dup -> x0.5)
            const int r = 64 + (k - 8);
            float s0 = 0.0f;
#pragma unroll
            for (int w = 0; w < NW; w++) s0 += wp[w][r] + wp[w][NTRI + r];
            val = 0.5f * s0;
        } else {
            int cls, r;
            if (k <= 7)            { cls = 0; r = k * (k + 1) / 2 + q; }
            else if (q >= 8)       { cls = 1; const int kk = 15 - q;
                                     r = kk * (kk + 1) / 2 + (15 - k); }
            else if (k + q < 15)   { cls = 0; r = 64 - (15 - k) * (16 - k) / 2 + q; }
            else /* k+q > 15 */    { cls = 1; r = 64 - q * (q + 1) / 2 + (15 - k); }
            float s0 = 0.0f;
#pragma unroll
            for (int w = 0; w < NW; w++) s0 += wp[w][cls * NTRI + r];
            val = s0;
        }
        if (k == q) val += 1.0f + 1e-6f;                 // I + jitter
        sM[k][q] = val;
        sM[q][k] = val;
    } else if (t < 152) {                                // wv merge
        const int k = t - 136;
        const int src = (k < 8) ? k : (8 + (15 - k));
        float s0 = 0.0f;
#pragma unroll
        for (int w = 0; w < NW; w++) s0 += wpv[w][src];
        sw[k] = s0;
    } else if (t < 159) {                                // stats merge c=0..6
        const int c = t - 152;
        if (c == 5) {
            float s0 = 3.402823466e38f;
#pragma unroll
            for (int w = 0; w < NW; w++) s0 = fminf(s0, wps[w][5]);
            g_sc[pat][5] = s0;
        } else {
            float s0 = 0.0f;
#pragma unroll
            for (int w = 0; w < NW; w++) s0 += wps[w][c];
            if (c == 0) { s0 *= 0.5f; srd[0] = s0; }     // rdr (pair-dup)
            if (c == 1) { s0 *= 0.5f; srd[1] = s0; }     // logdetD (pair-dup)
            if (c == 3 || c == 4) s0 *= 0.5f;            // ssg, srel (pair-dup)
            g_sc[pat][c] = s0;                           // sv2, bsum not dup'd
        }
    }
    __syncthreads();

    // ---- Cholesky + solve + NLL (warp 0) ----
    if (t < 32) {
        for (int j = 0; j < 16; j++) {
            if (t == j) sM[j][j] = sqrtf(sM[j][j]);
            __syncwarp();
            if (t > j && t < 16) sM[t][j] = sM[t][j] / sM[j][j];
            __syncwarp();
            if (t > j && t < 16) {
                const float lij = sM[t][j];
                for (int q = j + 1; q <= t; q++)
                    sM[t][q] -= lij * sM[q][j];
            }
            __syncwarp();
        }
        __syncwarp();
        if (t == 0) {
            float y[16];
            float yy = 0.0f, ldm = 0.0f;
            for (int r2 = 0; r2 < 16; r2++) {
                float acc = sw[r2];
                for (int q = 0; q < r2; q++) acc -= sM[r2][q] * y[q];
                y[r2] = acc / sM[r2][r2];
                yy  = fmaf(y[r2], y[r2], yy);
                ldm += __logf(sM[r2][r2]);
            }
            const float quad = srd[0] - yy;
            g_nll[pat] = 0.5f * (quad + srd[1] + 2.0f * ldm + GCONST)
                         * (1.0f / (float)DD);
        }
    }
}

// ---------------------------------------------------------------------------
// Final reduction
// ---------------------------------------------------------------------------
__global__ void __launch_bounds__(512) final_kernel(float* __restrict__ out, int out_size)
{
    const int t = threadIdx.x;       // 512 threads, one per patch
    float nl   = g_nll[t];
    float bs   = g_sc[t][6];
    float sv2  = g_sc[t][2], ssg = g_sc[t][3], srel = g_sc[t][4];
    float rmin = g_sc[t][5];

#pragma unroll
    for (int off = 16; off > 0; off >>= 1) {
        nl   += __shfl_xor_sync(0xffffffffu, nl,   off);
        bs   += __shfl_xor_sync(0xffffffffu, bs,   off);
        sv2  += __shfl_xor_sync(0xffffffffu, sv2,  off);
        ssg  += __shfl_xor_sync(0xffffffffu, ssg,  off);
        srel += __shfl_xor_sync(0xffffffffu, srel, off);
        rmin  = fminf(rmin, __shfl_xor_sync(0xffffffffu, rmin, off));
    }
    __shared__ float sm[16][6];
    if ((t & 31) == 0) {
        const int w = t >> 5;
        sm[w][0] = nl; sm[w][1] = bs; sm[w][2] = sv2;
        sm[w][3] = ssg; sm[w][4] = srel; sm[w][5] = rmin;
    }
    __syncthreads();
    if (t < 16) {
        float a0 = sm[t][0], a1 = sm[t][1], a2 = sm[t][2];
        float a3 = sm[t][3], a4 = sm[t][4], a5 = sm[t][5];
#pragma unroll
        for (int off = 8; off > 0; off >>= 1) {
            a0 += __shfl_xor_sync(0xffffu, a0, off);
            a1 += __shfl_xor_sync(0xffffu, a1, off);
            a2 += __shfl_xor_sync(0xffffu, a2, off);
            a3 += __shfl_xor_sync(0xffffu, a3, off);
            a4 += __shfl_xor_sync(0xffffu, a4, off);
            a5  = fminf(a5, __shfl_xor_sync(0xffffu, a5, off));
        }
        if (t == 0) {
            const float recon = a0 * (1.0f / 512.0f);
            const float bnd   = a1 * (1.0f / 172032.0f);     // sum / (12288*14)
            const float rank  = a2 * (1.0f / 100663296.0f);  // mean(V^2)
            const float msig  = a3 * (1.0f / 6291456.0f);
            const float sgp2  = a4 * (1.0f / 6291456.0f);
            out[0] = recon + 0.1f * bnd + 0.01f * rank + 0.05f * sgp2;
            out[1] = recon;
            out[2] = bnd;
            out[3] = rank;
            out[4] = sgp2;
            out[5] = msig;
            out[6] = a5;
        }
    }
    __syncthreads();
    for (int q = t + ((t >= 7) ? 0 : 512); q < out_size; q += 512)
        if (q >= 7) out[q] = 0.0f;
}

// ---------------------------------------------------------------------------
extern "C" void kernel_launch(void* const* d_in, const int* in_sizes, int n_in,
                              void* d_out, int out_size)
{
    int vi = 3;
    for (int idx = 0; idx < n_in; idx++)
        if (in_sizes[idx] == 100663296) vi = idx;
    const float* rest[3] = {nullptr, nullptr, nullptr};
    int m = 0;
    for (int idx = 0; idx < n_in && m < 3; idx++)
        if (idx != vi) rest[m++] = (const float*)d_in[idx];
    const float* x0 = rest[0];
    const float* mu = rest[1];
    const float* sg = rest[2];
    const float* V  = (const float*)d_in[vi];

    pass1_kernel<<<BN, T1>>>(x0, mu, sg, V);
    final_kernel<<<1, 512>>>((float*)d_out, out_size);
}